// round 12
// baseline (speedup 1.0000x reference)
#include <cuda_runtime.h>
#include <cuda_bf16.h>
#include <math.h>

// Problem constants (hardcoded: B=2, H=W=512)
#define B   2
#define H   512
#define W   512
#define HW  (H*W)            // 262144
#define PH  (H+1)            // pooled rows = 513
#define PW  (W+1)            // pooled valid cols = 513
#define PWP 516              // padded pooled row stride (cols 513..515 are zero)
#define PSZ ((size_t)PH * PWP)

// Scratch (static device memory; allocation APIs are forbidden)
__device__ float g_pooled[(size_t)B * 8 * PSZ];   // (B,8,513,516)  ~17 MB

__device__ __forceinline__ float fsqrt_fast(float x) {
    float r;
    asm("sqrt.approx.f32 %0, %1;" : "=f"(r) : "f"(x));
    return r;
}

// ----------------------------------------------------------------------------
// K1 (fused ang+pool): one block per (pooled row p, batch b).
// ----------------------------------------------------------------------------
__global__ __launch_bounds__(128)
void k_pool2(const float* __restrict__ x) {
    __shared__ __align__(16) float sx[6][512];     // 12288 B
    __shared__ __align__(16) float svc[8][520];    // 16640 B

    const int p = blockIdx.x;       // 0..512
    const int b = blockIdx.y;       // 0..1
    const int t = threadIdx.x;      // 0..127

    const float* xb = x + (size_t)b * HW;

#pragma unroll
    for (int s = 0; s < 6; s++) {
        const int rr = min(max(p - 3 + s, 0), H - 1);
        *(float4*)&sx[s][4 * t] = __ldg((const float4*)(xb + (size_t)rr * W) + t);
    }
    {
        float4* z = (float4*)svc;
        for (int k = t; k < 1040; k += 128) z[k] = make_float4(0.f, 0.f, 0.f, 0.f);
    }
    __syncthreads();

    const float TWO_PI = 6.283185307179586f;
#pragma unroll
    for (int ky = 0; ky < 4; ky++) {
        const int r = p - 2 + ky;
        if (r < 0 || r >= H) continue;
        const float wy = (ky == 0 || ky == 3) ? 0.25f : 0.75f;
#pragma unroll
        for (int m = 0; m < 4; m++) {
            const int c  = m * 128 + t;
            const int cm = max(c - 1, 0), cp = min(c + 1, W - 1);
            const float gx = 0.5f * (sx[ky + 1][cp] - sx[ky + 1][cm]);
            const float gy = 0.5f * (sx[ky + 2][c] - sx[ky][c]);

            const float mag = sqrtf(gx * gx + gy * gy + 1e-10f);
            const float ori = atan2f(gy, gx + 1e-10f) + TWO_PI;
            const float o   = ori * (8.0f / TWO_PI);
            const float bof = floorf(o);
            const float w1  = o - bof;
            const int b0 = ((int)bof) & 7;
            const int b1 = (b0 + 1) & 7;

            svc[b0][c + 2] += wy * (1.0f - w1) * mag;
            svc[b1][c + 2] += wy * w1 * mag;
        }
    }
    __syncthreads();

    const int q0 = 4 * t;
    float* pbase = g_pooled + (size_t)b * 8 * PSZ + (size_t)p * PWP;
    for (int d = 0; d < 8; d++) {
        const float4 A  = *(const float4*)&svc[d][q0];
        const float4 Bv = *(const float4*)&svc[d][q0 + 4];
        const float s0 = A.x,  s1 = A.y,  s2 = A.z, s3 = A.w;
        const float s4 = Bv.x, s5 = Bv.y, s6 = Bv.z;
        float4 o;
        o.x = 0.25f * (s0 + s3) + 0.75f * (s1 + s2);
        o.y = 0.25f * (s1 + s4) + 0.75f * (s2 + s3);
        o.z = 0.25f * (s2 + s5) + 0.75f * (s3 + s4);
        o.w = 0.25f * (s3 + s6) + 0.75f * (s4 + s5);
        *(float4*)(pbase + (size_t)d * PSZ + q0) = o;
        if (t == 0) {
            const float z = 0.25f * (svc[d][512] + svc[d][515])
                          + 0.75f * (svc[d][513] + svc[d][514]);
            *(float4*)(pbase + (size_t)d * PSZ + 512) = make_float4(z, 0.f, 0.f, 0.f);
        }
    }
}

// ----------------------------------------------------------------------------
// K2 (fused scal+write): 64x4-pixel tiles, 256 threads. Channel quarters live
//   in lane bits (quarter = tid & 3) so cross-quarter reductions are two
//   shfl.bfly ops -> ONE __syncthreads in the whole kernel; warps drift
//   independently through compute/store phases (no barrier convoy).
// ----------------------------------------------------------------------------
#define TXS 16
#define TYS 4
#define SPX 4
#define STILEX (TXS * SPX)      // 64
#define SROWS (TYS + 3)         // 7
#define SCOLS 68                // 67 valid + pad (16B-aligned row stride)

__global__ __launch_bounds__(256, 6)
void k_out(float* __restrict__ out) {
    __shared__ __align__(16) float tile[8][SROWS][SCOLS];   // 15232 B

    const int b  = blockIdx.z;
    const int j0 = blockIdx.x * STILEX;
    const int i0 = blockIdx.y * TYS;
    const int tid  = threadIdx.x;          // 0..255
    const int w    = tid >> 5;             // warp 0..7
    const int lane = tid & 31;

    // Loader: warp w owns channel d=w; 7 rows x 68 cols, division-free.
    {
        const int d = w;
        const float* pd = g_pooled + ((size_t)b * 8 + d) * PSZ;
#pragma unroll
        for (int r = 0; r < SROWS; r++) {
            const int pp = i0 - 1 + r;
            const bool pv = (pp >= 0) && (pp < PH);
            const float* prow = pd + (size_t)(pv ? pp : 0) * PWP;
#pragma unroll
            for (int cb = 0; cb < 3; cb++) {
                const int c = cb * 32 + lane;
                if (c < SCOLS) {
                    const int qq = j0 - 1 + c;     // max 514 < 516 (padded zero)
                    float v = 0.0f;
                    if (pv && qq >= 0) v = __ldg(prow + qq);
                    tile[d][r][c] = v;
                }
            }
        }
    }
    __syncthreads();        // the ONLY block-wide barrier

    // Compute mapping: quarter in lane bits 0..1; slot -> (x-group, row).
    const int quarter = tid & 3;           // 0..3 (within warp)
    const int slot    = tid >> 2;          // 0..63
    const int sx_     = slot & 15;         // x-group 0..15
    const int syc     = slot >> 4;         // row 0..3
    const int jl      = sx_ * SPX;
    const int i       = i0 + syc;
    const int d0      = quarter * 2;

    // Pass 1: partial sum of squares over this quarter's 2 channels
    float sq0 = 0.f, sq1 = 0.f, sq2 = 0.f, sq3 = 0.f;
#pragma unroll
    for (int dd = 0; dd < 2; dd++) {
        const int d = d0 + dd;
#pragma unroll
        for (int y = 0; y < 4; y++) {
            const float4 A  = *(const float4*)&tile[d][syc + y][jl];
            const float4 Bv = *(const float4*)&tile[d][syc + y][jl + 4];
            const float a0 = A.x,  a1 = A.y,  a2 = A.z,  a3 = A.w;
            const float a4 = Bv.x, a5 = Bv.y, a6 = Bv.z;
            sq0 = fmaf(a0, a0, sq0); sq0 = fmaf(a1, a1, sq0);
            sq0 = fmaf(a2, a2, sq0); sq0 = fmaf(a3, a3, sq0);
            sq1 = fmaf(a1, a1, sq1); sq1 = fmaf(a2, a2, sq1);
            sq1 = fmaf(a3, a3, sq1); sq1 = fmaf(a4, a4, sq1);
            sq2 = fmaf(a2, a2, sq2); sq2 = fmaf(a3, a3, sq2);
            sq2 = fmaf(a4, a4, sq2); sq2 = fmaf(a5, a5, sq2);
            sq3 = fmaf(a3, a3, sq3); sq3 = fmaf(a4, a4, sq3);
            sq3 = fmaf(a5, a5, sq3); sq3 = fmaf(a6, a6, sq3);
        }
    }
    // Butterfly reduce across the 4 quarter-lanes (bits 0..1)
    sq0 += __shfl_xor_sync(0xFFFFFFFF, sq0, 1);
    sq0 += __shfl_xor_sync(0xFFFFFFFF, sq0, 2);
    sq1 += __shfl_xor_sync(0xFFFFFFFF, sq1, 1);
    sq1 += __shfl_xor_sync(0xFFFFFFFF, sq1, 2);
    sq2 += __shfl_xor_sync(0xFFFFFFFF, sq2, 1);
    sq2 += __shfl_xor_sync(0xFFFFFFFF, sq2, 2);
    sq3 += __shfl_xor_sync(0xFFFFFFFF, sq3, 1);
    sq3 += __shfl_xor_sync(0xFFFFFFFF, sq3, 2);

    const float t0 = 0.2f * sqrtf(sq0);
    const float t1 = 0.2f * sqrtf(sq1);
    const float t2 = 0.2f * sqrtf(sq2);
    const float t3 = 0.2f * sqrtf(sq3);

    // Pass 2: partial clipped L1 over this quarter's channels
    float S0 = 0.f, S1 = 0.f, S2 = 0.f, S3 = 0.f;
#pragma unroll
    for (int dd = 0; dd < 2; dd++) {
        const int d = d0 + dd;
#pragma unroll
        for (int y = 0; y < 4; y++) {
            const float4 A  = *(const float4*)&tile[d][syc + y][jl];
            const float4 Bv = *(const float4*)&tile[d][syc + y][jl + 4];
            const float a0 = A.x,  a1 = A.y,  a2 = A.z,  a3 = A.w;
            const float a4 = Bv.x, a5 = Bv.y, a6 = Bv.z;
            S0 += fminf(a0, t0) + fminf(a1, t0) + fminf(a2, t0) + fminf(a3, t0);
            S1 += fminf(a1, t1) + fminf(a2, t1) + fminf(a3, t1) + fminf(a4, t1);
            S2 += fminf(a2, t2) + fminf(a3, t2) + fminf(a4, t2) + fminf(a5, t2);
            S3 += fminf(a3, t3) + fminf(a4, t3) + fminf(a5, t3) + fminf(a6, t3);
        }
    }
    S0 += __shfl_xor_sync(0xFFFFFFFF, S0, 1);
    S0 += __shfl_xor_sync(0xFFFFFFFF, S0, 2);
    S1 += __shfl_xor_sync(0xFFFFFFFF, S1, 1);
    S1 += __shfl_xor_sync(0xFFFFFFFF, S1, 2);
    S2 += __shfl_xor_sync(0xFFFFFFFF, S2, 1);
    S2 += __shfl_xor_sync(0xFFFFFFFF, S2, 2);
    S3 += __shfl_xor_sync(0xFFFFFFFF, S3, 1);
    S3 += __shfl_xor_sync(0xFFFFFFFF, S3, 2);

    const float inv0 = 1.0f / fmaxf(S0, 1e-20f);
    const float inv1 = 1.0f / fmaxf(S1, 1e-20f);
    const float inv2 = 1.0f / fmaxf(S2, 1e-20f);
    const float inv3 = 1.0f / fmaxf(S3, 1e-20f);

    // Pass 3: emit this quarter's 2 channels (32 output planes) as STG.128.
    // Per STG, the 8 lanes of each quarter write 128B contiguous per plane.
    float* ob = out + ((size_t)b * 128 * HW + (size_t)i * W + (j0 + jl));
#pragma unroll
    for (int dd = 0; dd < 2; dd++) {
        const int d = d0 + dd;
        float* obd = ob + (size_t)d * 16 * HW;
#pragma unroll
        for (int y = 0; y < 4; y++) {
            const float4 A  = *(const float4*)&tile[d][syc + y][jl];
            const float4 Bv = *(const float4*)&tile[d][syc + y][jl + 4];
            const float a0 = A.x,  a1 = A.y,  a2 = A.z,  a3 = A.w;
            const float a4 = Bv.x, a5 = Bv.y, a6 = Bv.z;
#pragma unroll
            for (int xk = 0; xk < 4; xk++) {
                float v0, v1, v2, v3;
                if (xk == 0)      { v0 = a0; v1 = a1; v2 = a2; v3 = a3; }
                else if (xk == 1) { v0 = a1; v1 = a2; v2 = a3; v3 = a4; }
                else if (xk == 2) { v0 = a2; v1 = a3; v2 = a4; v3 = a5; }
                else              { v0 = a3; v1 = a4; v2 = a5; v3 = a6; }
                float4 rs;
                rs.x = fsqrt_fast(fmaf(fminf(v0, t0), inv0, 1e-10f));
                rs.y = fsqrt_fast(fmaf(fminf(v1, t1), inv1, 1e-10f));
                rs.z = fsqrt_fast(fmaf(fminf(v2, t2), inv2, 1e-10f));
                rs.w = fsqrt_fast(fmaf(fminf(v3, t3), inv3, 1e-10f));
                __stcs((float4*)&obd[(size_t)(y * 4 + xk) * HW], rs);
            }
        }
    }
}

// ----------------------------------------------------------------------------
extern "C" void kernel_launch(void* const* d_in, const int* in_sizes, int n_in,
                              void* d_out, int out_size) {
    const float* x = (const float*)d_in[0];
    float* out = (float*)d_out;

    dim3 g1(PH, B);                        // (513, 2)
    dim3 g2(W / STILEX, H / TYS, B);       // (8, 128, 2) = 2048 blocks

    k_pool2<<<g1, 128>>>(x);
    k_out<<<g2, 256>>>(out);
}

// round 13
// speedup vs baseline: 1.4139x; 1.4139x over previous
#include <cuda_runtime.h>
#include <cuda_bf16.h>
#include <math.h>

// Problem constants (hardcoded: B=2, H=W=512)
#define B   2
#define H   512
#define W   512
#define HW  (H*W)            // 262144
#define PH  (H+1)            // pooled rows = 513
#define PW  (W+1)            // pooled valid cols = 513
#define PWP 516              // padded pooled row stride (cols 513..515 are zero)
#define PSZ ((size_t)PH * PWP)

// Scratch (static device memory; allocation APIs are forbidden)
__device__ float g_pooled[(size_t)B * 8 * PSZ];   // (B,8,513,516)  ~17 MB

__device__ __forceinline__ float fsqrt_fast(float x) {
    float r;
    asm("sqrt.approx.f32 %0, %1;" : "=f"(r) : "f"(x));
    return r;
}

// ----------------------------------------------------------------------------
// K1 (fused ang+pool): one block per (pooled row p, batch b).
// ----------------------------------------------------------------------------
__global__ __launch_bounds__(128)
void k_pool2(const float* __restrict__ x) {
    __shared__ __align__(16) float sx[6][512];     // 12288 B
    __shared__ __align__(16) float svc[8][520];    // 16640 B

    const int p = blockIdx.x;       // 0..512
    const int b = blockIdx.y;       // 0..1
    const int t = threadIdx.x;      // 0..127

    const float* xb = x + (size_t)b * HW;

#pragma unroll
    for (int s = 0; s < 6; s++) {
        const int rr = min(max(p - 3 + s, 0), H - 1);
        *(float4*)&sx[s][4 * t] = __ldg((const float4*)(xb + (size_t)rr * W) + t);
    }
    {
        float4* z = (float4*)svc;
        for (int k = t; k < 1040; k += 128) z[k] = make_float4(0.f, 0.f, 0.f, 0.f);
    }
    __syncthreads();

    const float TWO_PI = 6.283185307179586f;
#pragma unroll
    for (int ky = 0; ky < 4; ky++) {
        const int r = p - 2 + ky;
        if (r < 0 || r >= H) continue;
        const float wy = (ky == 0 || ky == 3) ? 0.25f : 0.75f;
#pragma unroll
        for (int m = 0; m < 4; m++) {
            const int c  = m * 128 + t;
            const int cm = max(c - 1, 0), cp = min(c + 1, W - 1);
            const float gx = 0.5f * (sx[ky + 1][cp] - sx[ky + 1][cm]);
            const float gy = 0.5f * (sx[ky + 2][c] - sx[ky][c]);

            const float mag = sqrtf(gx * gx + gy * gy + 1e-10f);
            const float ori = atan2f(gy, gx + 1e-10f) + TWO_PI;
            const float o   = ori * (8.0f / TWO_PI);
            const float bof = floorf(o);
            const float w1  = o - bof;
            const int b0 = ((int)bof) & 7;
            const int b1 = (b0 + 1) & 7;

            svc[b0][c + 2] += wy * (1.0f - w1) * mag;
            svc[b1][c + 2] += wy * w1 * mag;
        }
    }
    __syncthreads();

    const int q0 = 4 * t;
    float* pbase = g_pooled + (size_t)b * 8 * PSZ + (size_t)p * PWP;
    for (int d = 0; d < 8; d++) {
        const float4 A  = *(const float4*)&svc[d][q0];
        const float4 Bv = *(const float4*)&svc[d][q0 + 4];
        const float s0 = A.x,  s1 = A.y,  s2 = A.z, s3 = A.w;
        const float s4 = Bv.x, s5 = Bv.y, s6 = Bv.z;
        float4 o;
        o.x = 0.25f * (s0 + s3) + 0.75f * (s1 + s2);
        o.y = 0.25f * (s1 + s4) + 0.75f * (s2 + s3);
        o.z = 0.25f * (s2 + s5) + 0.75f * (s3 + s4);
        o.w = 0.25f * (s3 + s6) + 0.75f * (s4 + s5);
        *(float4*)(pbase + (size_t)d * PSZ + q0) = o;
        if (t == 0) {
            const float z = 0.25f * (svc[d][512] + svc[d][515])
                          + 0.75f * (svc[d][513] + svc[d][514]);
            *(float4*)(pbase + (size_t)d * PSZ + 512) = make_float4(z, 0.f, 0.f, 0.f);
        }
    }
}

// ----------------------------------------------------------------------------
// K2 (fused scal+write): R10 structure (proven 57.2us): 64x4-pixel tiles,
//   256 threads, quarter = tid>>6 (warp-uniform channel -> conflict-free LDS,
//   warp-contiguous stores), smem cross-quarter reduction. Single change vs
//   R10: __launch_bounds__(256, 8) to reach 64 warps/SM theoretical.
// ----------------------------------------------------------------------------
#define TXS 16
#define TYS 4
#define SPX 4
#define STILEX (TXS * SPX)      // 64
#define SROWS (TYS + 3)         // 7
#define SCOLS 68                // 67 valid + pad (16B-aligned row stride)

__global__ __launch_bounds__(256, 8)
void k_out(float* __restrict__ out) {
    __shared__ __align__(16) float tile[8][SROWS][SCOLS];   // 15232 B
    __shared__ __align__(16) float red[4][64][4];           // 4096 B

    const int b  = blockIdx.z;
    const int j0 = blockIdx.x * STILEX;
    const int i0 = blockIdx.y * TYS;
    const int tid  = threadIdx.x;          // 0..255
    const int w    = tid >> 5;             // warp 0..7
    const int lane = tid & 31;

    // Loader: warp w owns channel d=w; 7 rows x 68 cols, division-free.
    {
        const int d = w;
        const float* pd = g_pooled + ((size_t)b * 8 + d) * PSZ;
#pragma unroll
        for (int r = 0; r < SROWS; r++) {
            const int pp = i0 - 1 + r;
            const bool pv = (pp >= 0) && (pp < PH);
            const float* prow = pd + (size_t)(pv ? pp : 0) * PWP;
#pragma unroll
            for (int cb = 0; cb < 3; cb++) {
                const int c = cb * 32 + lane;
                if (c < SCOLS) {
                    const int qq = j0 - 1 + c;     // max 514 < 516 (padded zero)
                    float v = 0.0f;
                    if (pv && qq >= 0) v = __ldg(prow + qq);
                    tile[d][r][c] = v;
                }
            }
        }
    }
    __syncthreads();

    // Compute mapping: quarter owns channels {2q, 2q+1}; slot -> (x-group, row)
    const int quarter = tid >> 6;          // 0..3 (warp-uniform)
    const int slot    = tid & 63;          // 0..63
    const int sx_     = slot & 15;         // x-group 0..15
    const int syc     = slot >> 4;         // row 0..3
    const int jl      = sx_ * SPX;
    const int i       = i0 + syc;
    const int d0      = quarter * 2;

    // Pass 1: partial sum of squares over this quarter's 2 channels
    float sq0 = 0.f, sq1 = 0.f, sq2 = 0.f, sq3 = 0.f;
#pragma unroll
    for (int dd = 0; dd < 2; dd++) {
        const int d = d0 + dd;
#pragma unroll
        for (int y = 0; y < 4; y++) {
            const float4 A  = *(const float4*)&tile[d][syc + y][jl];
            const float4 Bv = *(const float4*)&tile[d][syc + y][jl + 4];
            const float a0 = A.x,  a1 = A.y,  a2 = A.z,  a3 = A.w;
            const float a4 = Bv.x, a5 = Bv.y, a6 = Bv.z;
            sq0 = fmaf(a0, a0, sq0); sq0 = fmaf(a1, a1, sq0);
            sq0 = fmaf(a2, a2, sq0); sq0 = fmaf(a3, a3, sq0);
            sq1 = fmaf(a1, a1, sq1); sq1 = fmaf(a2, a2, sq1);
            sq1 = fmaf(a3, a3, sq1); sq1 = fmaf(a4, a4, sq1);
            sq2 = fmaf(a2, a2, sq2); sq2 = fmaf(a3, a3, sq2);
            sq2 = fmaf(a4, a4, sq2); sq2 = fmaf(a5, a5, sq2);
            sq3 = fmaf(a3, a3, sq3); sq3 = fmaf(a4, a4, sq3);
            sq3 = fmaf(a5, a5, sq3); sq3 = fmaf(a6, a6, sq3);
        }
    }
    *(float4*)&red[quarter][slot][0] = make_float4(sq0, sq1, sq2, sq3);
    __syncthreads();
    {
        const float4 r0 = *(const float4*)&red[0][slot][0];
        const float4 r1 = *(const float4*)&red[1][slot][0];
        const float4 r2 = *(const float4*)&red[2][slot][0];
        const float4 r3 = *(const float4*)&red[3][slot][0];
        sq0 = r0.x + r1.x + r2.x + r3.x;
        sq1 = r0.y + r1.y + r2.y + r3.y;
        sq2 = r0.z + r1.z + r2.z + r3.z;
        sq3 = r0.w + r1.w + r2.w + r3.w;
    }
    const float t0 = 0.2f * sqrtf(sq0);
    const float t1 = 0.2f * sqrtf(sq1);
    const float t2 = 0.2f * sqrtf(sq2);
    const float t3 = 0.2f * sqrtf(sq3);

    // Pass 2: partial clipped L1 over this quarter's channels
    float S0 = 0.f, S1 = 0.f, S2 = 0.f, S3 = 0.f;
#pragma unroll
    for (int dd = 0; dd < 2; dd++) {
        const int d = d0 + dd;
#pragma unroll
        for (int y = 0; y < 4; y++) {
            const float4 A  = *(const float4*)&tile[d][syc + y][jl];
            const float4 Bv = *(const float4*)&tile[d][syc + y][jl + 4];
            const float a0 = A.x,  a1 = A.y,  a2 = A.z,  a3 = A.w;
            const float a4 = Bv.x, a5 = Bv.y, a6 = Bv.z;
            S0 += fminf(a0, t0) + fminf(a1, t0) + fminf(a2, t0) + fminf(a3, t0);
            S1 += fminf(a1, t1) + fminf(a2, t1) + fminf(a3, t1) + fminf(a4, t1);
            S2 += fminf(a2, t2) + fminf(a3, t2) + fminf(a4, t2) + fminf(a5, t2);
            S3 += fminf(a3, t3) + fminf(a4, t3) + fminf(a5, t3) + fminf(a6, t3);
        }
    }
    __syncthreads();   // red reuse (all pass-1 reads complete)
    *(float4*)&red[quarter][slot][0] = make_float4(S0, S1, S2, S3);
    __syncthreads();
    {
        const float4 r0 = *(const float4*)&red[0][slot][0];
        const float4 r1 = *(const float4*)&red[1][slot][0];
        const float4 r2 = *(const float4*)&red[2][slot][0];
        const float4 r3 = *(const float4*)&red[3][slot][0];
        S0 = r0.x + r1.x + r2.x + r3.x;
        S1 = r0.y + r1.y + r2.y + r3.y;
        S2 = r0.z + r1.z + r2.z + r3.z;
        S3 = r0.w + r1.w + r2.w + r3.w;
    }
    const float inv0 = 1.0f / fmaxf(S0, 1e-20f);
    const float inv1 = 1.0f / fmaxf(S1, 1e-20f);
    const float inv2 = 1.0f / fmaxf(S2, 1e-20f);
    const float inv3 = 1.0f / fmaxf(S3, 1e-20f);

    // Pass 3: emit this quarter's 2 channels (32 output planes) as STG.128.
    float* ob = out + ((size_t)b * 128 * HW + (size_t)i * W + (j0 + jl));
#pragma unroll
    for (int dd = 0; dd < 2; dd++) {
        const int d = d0 + dd;
        float* obd = ob + (size_t)d * 16 * HW;
#pragma unroll
        for (int y = 0; y < 4; y++) {
            const float4 A  = *(const float4*)&tile[d][syc + y][jl];
            const float4 Bv = *(const float4*)&tile[d][syc + y][jl + 4];
            const float a0 = A.x,  a1 = A.y,  a2 = A.z,  a3 = A.w;
            const float a4 = Bv.x, a5 = Bv.y, a6 = Bv.z;
#pragma unroll
            for (int xk = 0; xk < 4; xk++) {
                float v0, v1, v2, v3;
                if (xk == 0)      { v0 = a0; v1 = a1; v2 = a2; v3 = a3; }
                else if (xk == 1) { v0 = a1; v1 = a2; v2 = a3; v3 = a4; }
                else if (xk == 2) { v0 = a2; v1 = a3; v2 = a4; v3 = a5; }
                else              { v0 = a3; v1 = a4; v2 = a5; v3 = a6; }
                float4 rs;
                rs.x = fsqrt_fast(fmaf(fminf(v0, t0), inv0, 1e-10f));
                rs.y = fsqrt_fast(fmaf(fminf(v1, t1), inv1, 1e-10f));
                rs.z = fsqrt_fast(fmaf(fminf(v2, t2), inv2, 1e-10f));
                rs.w = fsqrt_fast(fmaf(fminf(v3, t3), inv3, 1e-10f));
                __stcs((float4*)&obd[(size_t)(y * 4 + xk) * HW], rs);
            }
        }
    }
}

// ----------------------------------------------------------------------------
extern "C" void kernel_launch(void* const* d_in, const int* in_sizes, int n_in,
                              void* d_out, int out_size) {
    const float* x = (const float*)d_in[0];
    float* out = (float*)d_out;

    dim3 g1(PH, B);                        // (513, 2)
    dim3 g2(W / STILEX, H / TYS, B);       // (8, 128, 2) = 2048 blocks

    k_pool2<<<g1, 128>>>(x);
    k_out<<<g2, 256>>>(out);
}